// round 1
// baseline (speedup 1.0000x reference)
#include <cuda_runtime.h>
#include <math.h>

#define BB 8
#define NN 2048
#define CC 512
#define KK 8
#define TOPK 2
#define EPSF 1e-6f
#define GENO_RATIO 0.1f

// ---------------- scratch (device globals; no allocation allowed) ----------------
__device__ int   g_cnt[BB][KK];          // routed token count per (b,k)
__device__ int   g_idx[BB][KK][NN];      // token indices per (b,k)
__device__ float g_wgt[BB][KK][NN];      // routing weights per (b,k)
__device__ float g_mass[BB][KK];         // sum of weights per (b,k)
__device__ float g_hw[BB][KK][CC];       // weighted sum of relu hidden per (b,k)
__device__ float g_glog[BB][KK];         // geno logit contribution per (b,k)

// ---------------- zero scratch ----------------
__global__ void zero_kernel() {
    int t = blockIdx.x * blockDim.x + threadIdx.x;
    if (t < BB * KK) {
        ((int*)g_cnt)[t] = 0;
        ((float*)g_mass)[t] = 0.f;
    }
    const int total = BB * KK * CC;
    float* hw = &g_hw[0][0][0];
    for (int i = t; i < total; i += gridDim.x * blockDim.x) hw[i] = 0.f;
}

// ---------------- geno logits: g_glog[b][k] = 0.1*(geno_vec[b]@geno_w[:,k]+geno_b[k]) ----
__global__ void glog_kernel(const float* __restrict__ geno_vec,
                            const float* __restrict__ geno_w,
                            const float* __restrict__ geno_b) {
    int t = threadIdx.x;
    if (t >= BB * KK) return;
    int b = t / KK, k = t % KK;
    float acc = 0.f;
    for (int c = 0; c < CC; c++) acc += geno_vec[b * CC + c] * geno_w[c * KK + k];
    g_glog[b][k] = GENO_RATIO * (acc + geno_b[k]);
}

// ---------------- gating: logits, top-2, softmax weights, scatter ----------------
__global__ void gate_kernel(const float* __restrict__ tokens,
                            const float* __restrict__ gate_w,
                            const float* __restrict__ gate_b) {
    int warp = (blockIdx.x * blockDim.x + threadIdx.x) >> 5;
    int lane = threadIdx.x & 31;
    if (warp >= BB * NN) return;
    int b = warp / NN, n = warp % NN;
    const float* x = tokens + (size_t)(b * NN + n) * CC;

    float acc[KK];
#pragma unroll
    for (int k = 0; k < KK; k++) acc[k] = 0.f;
    for (int c = lane; c < CC; c += 32) {
        float xv = x[c];
        const float* gw = gate_w + c * KK;
#pragma unroll
        for (int k = 0; k < KK; k++) acc[k] += xv * gw[k];
    }
#pragma unroll
    for (int k = 0; k < KK; k++) {
#pragma unroll
        for (int off = 16; off; off >>= 1)
            acc[k] += __shfl_xor_sync(0xffffffffu, acc[k], off);
    }

    if (lane == 0) {
        float lg[KK];
#pragma unroll
        for (int k = 0; k < KK; k++) lg[k] = acc[k] + gate_b[k] + g_glog[b][k];
        // GATE_TEMP = 1 -> identity

        // top-2 (ties -> lowest index first, matching lax.top_k)
        int i0 = 0; float v0 = lg[0];
#pragma unroll
        for (int k = 1; k < KK; k++) if (lg[k] > v0) { v0 = lg[k]; i0 = k; }
        int i1 = -1; float v1 = -3.4e38f;
#pragma unroll
        for (int k = 0; k < KK; k++) if (k != i0 && lg[k] > v1) { v1 = lg[k]; i1 = k; }

        // softmax over (v0, v1), v0 >= v1
        float e1 = __expf(v1 - v0);
        float inv = 1.f / (1.f + e1);
        float w0 = inv, w1 = e1 * inv;
        w0 = fmaxf(w0, EPSF); w1 = fmaxf(w1, EPSF);
        float s = 1.f / (w0 + w1);
        w0 *= s; w1 *= s;

        int p0 = atomicAdd(&g_cnt[b][i0], 1);
        g_idx[b][i0][p0] = n; g_wgt[b][i0][p0] = w0;
        atomicAdd(&g_mass[b][i0], w0);
        int p1 = atomicAdd(&g_cnt[b][i1], 1);
        g_idx[b][i1][p1] = n; g_wgt[b][i1][p1] = w1;
        atomicAdd(&g_mass[b][i1], w1);
    }
}

// ---------------- gathered FFN layer 1: hw[b,k,d] += sum_m w_m * relu(x_m @ w1[k] + b1[k])[d]
#define TM 64
#define TN 64
#define TC 16

__global__ __launch_bounds__(256) void ffn1_kernel(const float* __restrict__ tokens,
                                                   const float* __restrict__ w1,
                                                   const float* __restrict__ b1) {
    const int bk = blockIdx.z;
    const int b = bk / KK, k = bk % KK;
    const int cnt = g_cnt[b][k];
    const int m0 = blockIdx.y * TM;
    if (m0 >= cnt) return;
    const int d0 = blockIdx.x * TN;

    __shared__ float Xs[TC][TM + 4];
    __shared__ float W1s[TC][TN + 4];
    __shared__ float red[16][TN];
    __shared__ int   ns[TM];
    __shared__ float wts[TM];

    const int tid = threadIdx.x;
    if (tid < TM) {
        int m = m0 + tid;
        if (m < cnt) { ns[tid] = g_idx[b][k][m]; wts[tid] = g_wgt[b][k][m]; }
        else         { ns[tid] = -1;             wts[tid] = 0.f; }
    }
    __syncthreads();

    const int ty = tid >> 4;   // 0..15 -> 4 token rows each
    const int tx = tid & 15;   // 0..15 -> 4 d cols each

    float accv[4][4];
#pragma unroll
    for (int i = 0; i < 4; i++)
#pragma unroll
        for (int j = 0; j < 4; j++) accv[i][j] = 0.f;

    // load indices for this thread's X fetch
    const int lm = tid >> 2;          // 0..63
    const int lcs = (tid & 3) * 4;    // 0,4,8,12
    const int wc = tid >> 4;          // 0..15
    const int wds = (tid & 15) * 4;   // 0..60
    const int ln = ns[lm];
    const float* xrow = (ln >= 0) ? (tokens + ((size_t)(b * NN + ln)) * CC) : tokens;
    const float* w1k = w1 + (size_t)k * CC * CC;

    for (int c0 = 0; c0 < CC; c0 += TC) {
        // X tile (transposed into smem)
        float4 v = make_float4(0.f, 0.f, 0.f, 0.f);
        if (ln >= 0) v = *(const float4*)(xrow + c0 + lcs);
        Xs[lcs + 0][lm] = v.x;
        Xs[lcs + 1][lm] = v.y;
        Xs[lcs + 2][lm] = v.z;
        Xs[lcs + 3][lm] = v.w;
        // W1 tile
        *(float4*)&W1s[wc][wds] = *(const float4*)(w1k + (size_t)(c0 + wc) * CC + d0 + wds);
        __syncthreads();

#pragma unroll
        for (int cc = 0; cc < TC; cc++) {
            float4 xv = *(const float4*)&Xs[cc][ty * 4];
            float4 wv = *(const float4*)&W1s[cc][tx * 4];
            accv[0][0] += xv.x * wv.x; accv[0][1] += xv.x * wv.y;
            accv[0][2] += xv.x * wv.z; accv[0][3] += xv.x * wv.w;
            accv[1][0] += xv.y * wv.x; accv[1][1] += xv.y * wv.y;
            accv[1][2] += xv.y * wv.z; accv[1][3] += xv.y * wv.w;
            accv[2][0] += xv.z * wv.x; accv[2][1] += xv.z * wv.y;
            accv[2][2] += xv.z * wv.z; accv[2][3] += xv.z * wv.w;
            accv[3][0] += xv.w * wv.x; accv[3][1] += xv.w * wv.y;
            accv[3][2] += xv.w * wv.z; accv[3][3] += xv.w * wv.w;
        }
        __syncthreads();
    }

    // epilogue: relu(acc + b1) * w_row, reduce over rows
    float wr[4];
#pragma unroll
    for (int i = 0; i < 4; i++) wr[i] = wts[ty * 4 + i];
    float b1v[4];
#pragma unroll
    for (int j = 0; j < 4; j++) b1v[j] = b1[k * CC + d0 + tx * 4 + j];

#pragma unroll
    for (int j = 0; j < 4; j++) {
        float s = 0.f;
#pragma unroll
        for (int i = 0; i < 4; i++)
            s += fmaxf(accv[i][j] + b1v[j], 0.f) * wr[i];
        red[ty][tx * 4 + j] = s;
    }
    __syncthreads();
    if (tid < TN) {
        float s = 0.f;
#pragma unroll
        for (int r = 0; r < 16; r++) s += red[r][tid];
        atomicAdd(&g_hw[b][k][d0 + tid], s);
    }
}

// ---------------- centers: (hw @ w2[k] + b2*mass)/max(mass,eps) ----------------
__global__ void centers_kernel(const float* __restrict__ w2,
                               const float* __restrict__ b2,
                               float* __restrict__ out, int out_size) {
    int b = blockIdx.x / KK, k = blockIdx.x % KK;
    __shared__ float hws[CC];
    int t = threadIdx.x;
    for (int i = t; i < CC; i += blockDim.x) hws[i] = g_hw[b][k][i];
    __syncthreads();
    float mass = g_mass[b][k];
    float inv = 1.f / fmaxf(mass, EPSF);
    const float* w2k = w2 + (size_t)k * CC * CC;
    for (int e = t; e < CC; e += blockDim.x) {
        float acc = 0.f;
        const float* wp = w2k + e;
#pragma unroll 8
        for (int d = 0; d < CC; d++) acc += hws[d] * wp[d * CC];
        float val = (acc + b2[k * CC + e] * mass) * inv;
        int o = (b * KK + k) * CC + e;
        if (o < out_size) out[o] = val;
    }
}

// ---------------- load-balance loss ----------------
__global__ void loss_kernel(float* __restrict__ out, int out_size) {
    if (threadIdx.x != 0 || blockIdx.x != 0) return;
    float usage[KK];
    float mean = 0.f;
#pragma unroll
    for (int k = 0; k < KK; k++) {
        int s = 0;
        for (int b = 0; b < BB; b++) s += g_cnt[b][k];
        usage[k] = (float)s / (float)(BB * NN);
        mean += usage[k];
    }
    mean /= (float)KK;
    float var = 0.f;
#pragma unroll
    for (int k = 0; k < KK; k++) {
        float d = usage[k] - mean;
        var += d * d;
    }
    var /= (float)KK;  // population variance
    float denom = mean + EPSF;
    out[out_size - 1] = var / (denom * denom);
}

// ---------------- launch ----------------
extern "C" void kernel_launch(void* const* d_in, const int* in_sizes, int n_in,
                              void* d_out, int out_size) {
    const float* tokens   = (const float*)d_in[0];
    const float* geno_vec = (const float*)d_in[1];
    const float* gate_w   = (const float*)d_in[2];
    const float* gate_b   = (const float*)d_in[3];
    const float* geno_w   = (const float*)d_in[4];
    const float* geno_b   = (const float*)d_in[5];
    const float* w1       = (const float*)d_in[6];
    const float* b1       = (const float*)d_in[7];
    const float* w2       = (const float*)d_in[8];
    const float* b2       = (const float*)d_in[9];
    float* out = (float*)d_out;

    zero_kernel<<<64, 512>>>();
    glog_kernel<<<1, 64>>>(geno_vec, geno_w, geno_b);
    {
        int warps = BB * NN;                 // one warp per token
        int threads = 256;
        int blocks = (warps * 32 + threads - 1) / threads;
        gate_kernel<<<blocks, threads>>>(tokens, gate_w, gate_b);
    }
    {
        dim3 grid(CC / TN, NN / TM, BB * KK); // 8 x 32 x 64 (most m-tiles exit early)
        ffn1_kernel<<<grid, 256>>>(tokens, w1, b1);
    }
    centers_kernel<<<BB * KK, 256>>>(w2, b2, out, out_size);
    loss_kernel<<<1, 1>>>(out, out_size);
}

// round 3
// speedup vs baseline: 2.1639x; 2.1639x over previous
#include <cuda_runtime.h>
#include <math.h>
#include <cstdint>

#define BB 8
#define NN 2048
#define CC 512
#define KK 8
#define EPSF 1e-6f
#define GENO_RATIO 0.1f

// ---------------- scratch (device globals) ----------------
__device__ int   g_cnt[BB][KK];
__device__ int   g_idx[BB][KK][NN];
__device__ float g_wgt[BB][KK][NN];
__device__ float g_mass[BB][KK];
__device__ float g_hw[BB][KK][CC];
__device__ float g_glog[BB][KK];

__device__ __forceinline__ float tf32r(float x) {
    uint32_t u;
    asm("cvt.rna.tf32.f32 %0, %1;" : "=r"(u) : "f"(x));
    return __uint_as_float(u);
}

// ---------------- simple kernels ----------------
__global__ void zero_kernel() {
    int t = blockIdx.x * blockDim.x + threadIdx.x;
    if (t < BB * KK) { ((int*)g_cnt)[t] = 0; ((float*)g_mass)[t] = 0.f; }
    float* hw = &g_hw[0][0][0];
    for (int i = t; i < BB * KK * CC; i += gridDim.x * blockDim.x) hw[i] = 0.f;
}

__global__ void glog_kernel(const float* __restrict__ geno_vec,
                            const float* __restrict__ geno_w,
                            const float* __restrict__ geno_b) {
    int t = threadIdx.x;
    if (t >= BB * KK) return;
    int b = t / KK, k = t % KK;
    float acc = 0.f;
    for (int c = 0; c < CC; c++) acc += geno_vec[b * CC + c] * geno_w[c * KK + k];
    g_glog[b][k] = GENO_RATIO * (acc + geno_b[k]);
}

// ---------------- gating ----------------
__global__ __launch_bounds__(256) void gate_kernel(const float* __restrict__ tokens,
                                                   const float* __restrict__ gate_w,
                                                   const float* __restrict__ gate_b) {
    __shared__ float gwT[KK][CC];  // 16KB transposed gate weights
    int tid = threadIdx.x;
    for (int i = tid; i < CC * KK; i += 256) gwT[i & 7][i >> 3] = gate_w[i];
    __syncthreads();

    int warp = blockIdx.x * 8 + (tid >> 5);
    int lane = tid & 31;
    if (warp >= BB * NN) return;
    int b = warp / NN, n = warp % NN;
    const float* x = tokens + (size_t)(b * NN + n) * CC;

    float acc[KK];
#pragma unroll
    for (int k = 0; k < KK; k++) acc[k] = 0.f;
#pragma unroll
    for (int i = 0; i < 4; i++) {
        int c = i * 128 + lane * 4;
        float4 xv = *(const float4*)(x + c);
#pragma unroll
        for (int k = 0; k < KK; k++) {
            float4 gv = *(const float4*)&gwT[k][c];
            acc[k] += xv.x * gv.x + xv.y * gv.y + xv.z * gv.z + xv.w * gv.w;
        }
    }
#pragma unroll
    for (int k = 0; k < KK; k++) {
#pragma unroll
        for (int off = 16; off; off >>= 1)
            acc[k] += __shfl_xor_sync(0xffffffffu, acc[k], off);
    }

    if (lane == 0) {
        float lg[KK];
#pragma unroll
        for (int k = 0; k < KK; k++) lg[k] = acc[k] + gate_b[k] + g_glog[b][k];
        int i0 = 0; float v0 = lg[0];
#pragma unroll
        for (int k = 1; k < KK; k++) if (lg[k] > v0) { v0 = lg[k]; i0 = k; }
        int i1 = -1; float v1 = -3.4e38f;
#pragma unroll
        for (int k = 0; k < KK; k++) if (k != i0 && lg[k] > v1) { v1 = lg[k]; i1 = k; }
        float e1 = __expf(v1 - v0);
        float inv = 1.f / (1.f + e1);
        float w0 = fmaxf(inv, EPSF), w1v = fmaxf(e1 * inv, EPSF);
        float s = 1.f / (w0 + w1v);
        w0 *= s; w1v *= s;
        int p0 = atomicAdd(&g_cnt[b][i0], 1);
        g_idx[b][i0][p0] = n; g_wgt[b][i0][p0] = w0;
        atomicAdd(&g_mass[b][i0], w0);
        int p1 = atomicAdd(&g_cnt[b][i1], 1);
        g_idx[b][i1][p1] = n; g_wgt[b][i1][p1] = w1v;
        atomicAdd(&g_mass[b][i1], w1v);
    }
}

// ---------------- ffn1 via mma.sync tf32 ----------------
// D[m(token), n(d)] = X[m, c] @ w1[k][c, n]; fused relu+bias+weight row-reduce.
#define BM 128
#define BN 128
#define BKC 32
#define NSTAGE (CC / BKC)     // 16
#define XS_STRIDE (BM + 8)    // 136 floats (k-major X tile)
#define WS_STRIDE (BN + 8)    // 136 floats (k-major W tile)
#define XTILE_FLOATS (BKC * XS_STRIDE)
#define WTILE_FLOATS (BKC * WS_STRIDE)
#define STAGE_FLOATS (XTILE_FLOATS + WTILE_FLOATS)

__device__ __forceinline__ void mma1688(float* c, const uint32_t* a, const uint32_t* bf) {
    asm volatile(
        "mma.sync.aligned.m16n8k8.row.col.f32.tf32.tf32.f32 "
        "{%0,%1,%2,%3}, {%4,%5,%6,%7}, {%8,%9}, {%0,%1,%2,%3};"
        : "+f"(c[0]), "+f"(c[1]), "+f"(c[2]), "+f"(c[3])
        : "r"(a[0]), "r"(a[1]), "r"(a[2]), "r"(a[3]), "r"(bf[0]), "r"(bf[1]));
}

__global__ __launch_bounds__(256, 1) void ffn1_mma_kernel(const float* __restrict__ tokens,
                                                          const float* __restrict__ w1,
                                                          const float* __restrict__ b1) {
    extern __shared__ float smem[];
    const int bk = blockIdx.z;
    const int b = bk >> 3, k = bk & 7;
    const int cnt = g_cnt[b][k];
    const int m0 = blockIdx.y * BM;
    if (m0 >= cnt) return;
    const int d0 = blockIdx.x * BN;

    float* Xs0 = smem;
    float* Ws0 = smem + XTILE_FLOATS;
    float* Xs1 = smem + STAGE_FLOATS;
    float* Ws1 = smem + STAGE_FLOATS + XTILE_FLOATS;
    int*   ns_s = (int*)(smem + 2 * STAGE_FLOATS);
    float* wt_s = (float*)(ns_s + BM);

    const int tid = threadIdx.x;
    const int lane = tid & 31, wid = tid >> 5;
    const int wm = wid >> 2, wn = wid & 3;     // 2 x 4 warp grid
    const int l4 = lane >> 2, lm = lane & 3;

    if (tid < BM) {
        int m = m0 + tid;
        if (m < cnt) { ns_s[tid] = g_idx[b][k][m]; wt_s[tid] = g_wgt[b][k][m]; }
        else         { ns_s[tid] = -1;             wt_s[tid] = 0.f; }
    }
    __syncthreads();

    // loader mapping
    const int xm = tid >> 1;              // token row 0..127
    const int xjb = (tid & 1) * 4;        // float4 index base (0 or 4)
    const int xn = ns_s[xm];
    const float* xp = (xn >= 0) ? tokens + ((size_t)(b * NN + xn)) * CC : nullptr;
    const int wr = tid >> 3;              // w row (c) 0..31
    const int wjb = tid & 7;              // float4 col base
    const float* wp = w1 + ((size_t)k * CC + wr) * CC + d0;

    float4 xv[4], wv[4];
#define LOAD_STAGE(s) do {                                                        \
        int c0_ = (s) * BKC;                                                      \
        _Pragma("unroll")                                                         \
        for (int i = 0; i < 4; i++)                                               \
            xv[i] = xp ? *(const float4*)(xp + c0_ + (xjb + i) * 4)               \
                       : make_float4(0.f, 0.f, 0.f, 0.f);                         \
        _Pragma("unroll")                                                         \
        for (int i = 0; i < 4; i++)                                               \
            wv[i] = *(const float4*)(wp + (size_t)c0_ * CC + (wjb + i * 8) * 4);  \
    } while (0)

#define STORE_STAGE(Xst, Wst) do {                                                \
        _Pragma("unroll")                                                         \
        for (int i = 0; i < 4; i++) {                                             \
            int kl = (xjb + i) * 4;                                               \
            (Xst)[(kl + 0) * XS_STRIDE + xm] = tf32r(xv[i].x);                    \
            (Xst)[(kl + 1) * XS_STRIDE + xm] = tf32r(xv[i].y);                    \
            (Xst)[(kl + 2) * XS_STRIDE + xm] = tf32r(xv[i].z);                    \
            (Xst)[(kl + 3) * XS_STRIDE + xm] = tf32r(xv[i].w);                    \
        }                                                                         \
        _Pragma("unroll")                                                         \
        for (int i = 0; i < 4; i++) {                                             \
            float4 t;                                                             \
            t.x = tf32r(wv[i].x); t.y = tf32r(wv[i].y);                           \
            t.z = tf32r(wv[i].z); t.w = tf32r(wv[i].w);                           \
            *(float4*)((Wst) + wr * WS_STRIDE + (wjb + i * 8) * 4) = t;           \
        }                                                                         \
    } while (0)

    float acc[4][4][4];
#pragma unroll
    for (int mf = 0; mf < 4; mf++)
#pragma unroll
        for (int nf = 0; nf < 4; nf++)
#pragma unroll
            for (int q = 0; q < 4; q++) acc[mf][nf][q] = 0.f;

    LOAD_STAGE(0);
    STORE_STAGE(Xs0, Ws0);
    __syncthreads();

    for (int s = 0; s < NSTAGE; s++) {
        const float* Xst = (s & 1) ? Xs1 : Xs0;
        const float* Wst = (s & 1) ? Ws1 : Ws0;
        if (s + 1 < NSTAGE) LOAD_STAGE(s + 1);

#pragma unroll
        for (int kk = 0; kk < 4; kk++) {
            uint32_t a[4][4], bf[4][2];
            const float* xk0 = Xst + (kk * 8 + lm) * XS_STRIDE;
            const float* xk4 = Xst + (kk * 8 + lm + 4) * XS_STRIDE;
#pragma unroll
            for (int mf = 0; mf < 4; mf++) {
                int mrow = wm * 64 + mf * 16 + l4;
                a[mf][0] = __float_as_uint(xk0[mrow]);
                a[mf][1] = __float_as_uint(xk0[mrow + 8]);
                a[mf][2] = __float_as_uint(xk4[mrow]);
                a[mf][3] = __float_as_uint(xk4[mrow + 8]);
            }
            const float* wk0 = Wst + (kk * 8 + lm) * WS_STRIDE;
            const float* wk4 = Wst + (kk * 8 + lm + 4) * WS_STRIDE;
#pragma unroll
            for (int nf = 0; nf < 4; nf++) {
                int ncol = wn * 32 + nf * 8 + l4;
                bf[nf][0] = __float_as_uint(wk0[ncol]);
                bf[nf][1] = __float_as_uint(wk4[ncol]);
            }
#pragma unroll
            for (int mf = 0; mf < 4; mf++)
#pragma unroll
                for (int nf = 0; nf < 4; nf++)
                    mma1688(acc[mf][nf], a[mf], bf[nf]);
        }

        if (s + 1 < NSTAGE) {
            __syncthreads();
            if (s & 1) STORE_STAGE(Xs0, Ws0);
            else       STORE_STAGE(Xs1, Ws1);
            __syncthreads();
        }
    }

    // epilogue: relu(acc + b1) * wt, reduce over token rows
    float bias[4][2];
#pragma unroll
    for (int nf = 0; nf < 4; nf++)
#pragma unroll
        for (int j = 0; j < 2; j++)
            bias[nf][j] = __ldg(b1 + k * CC + d0 + wn * 32 + nf * 8 + lm * 2 + j);

    float part[4][2];
#pragma unroll
    for (int nf = 0; nf < 4; nf++) { part[nf][0] = 0.f; part[nf][1] = 0.f; }

#pragma unroll
    for (int mf = 0; mf < 4; mf++) {
        int r0 = wm * 64 + mf * 16 + l4;
        float w0 = wt_s[r0], w1r = wt_s[r0 + 8];
#pragma unroll
        for (int nf = 0; nf < 4; nf++)
#pragma unroll
            for (int j = 0; j < 2; j++)
                part[nf][j] += fmaxf(acc[mf][nf][j] + bias[nf][j], 0.f) * w0
                             + fmaxf(acc[mf][nf][2 + j] + bias[nf][j], 0.f) * w1r;
    }
#pragma unroll
    for (int off = 4; off < 32; off <<= 1)
#pragma unroll
        for (int nf = 0; nf < 4; nf++)
#pragma unroll
            for (int j = 0; j < 2; j++)
                part[nf][j] += __shfl_xor_sync(0xffffffffu, part[nf][j], off);

    if (l4 == 0) {
        float* hw = &g_hw[b][k][0];
#pragma unroll
        for (int nf = 0; nf < 4; nf++)
#pragma unroll
            for (int j = 0; j < 2; j++)
                atomicAdd(hw + d0 + wn * 32 + nf * 8 + lm * 2 + j, part[nf][j]);
    }
}

// ---------------- centers ----------------
__global__ __launch_bounds__(512) void centers_kernel(const float* __restrict__ w2,
                                                      const float* __restrict__ b2,
                                                      float* __restrict__ out, int out_size) {
    int b = blockIdx.x / KK, k = blockIdx.x % KK;
    __shared__ float hws[CC];
    int e = threadIdx.x;
    hws[e] = g_hw[b][k][e];
    __syncthreads();
    float mass = g_mass[b][k];
    float inv = 1.f / fmaxf(mass, EPSF);
    const float* w2k = w2 + (size_t)k * CC * CC;
    float acc = 0.f;
#pragma unroll 8
    for (int d = 0; d < CC; d++) acc += hws[d] * w2k[(size_t)d * CC + e];
    float val = (acc + b2[k * CC + e] * mass) * inv;
    int o = (b * KK + k) * CC + e;
    if (o < out_size) out[o] = val;
}

__global__ void loss_kernel(float* __restrict__ out, int out_size) {
    if (threadIdx.x != 0 || blockIdx.x != 0) return;
    float usage[KK], mean = 0.f;
#pragma unroll
    for (int k = 0; k < KK; k++) {
        int s = 0;
        for (int b = 0; b < BB; b++) s += g_cnt[b][k];
        usage[k] = (float)s / (float)(BB * NN);
        mean += usage[k];
    }
    mean /= (float)KK;
    float var = 0.f;
#pragma unroll
    for (int k = 0; k < KK; k++) { float d = usage[k] - mean; var += d * d; }
    var /= (float)KK;
    float denom = mean + EPSF;
    out[out_size - 1] = var / (denom * denom);
}

// ---------------- launch ----------------
extern "C" void kernel_launch(void* const* d_in, const int* in_sizes, int n_in,
                              void* d_out, int out_size) {
    const float* tokens   = (const float*)d_in[0];
    const float* geno_vec = (const float*)d_in[1];
    const float* gate_w   = (const float*)d_in[2];
    const float* gate_b   = (const float*)d_in[3];
    const float* geno_w   = (const float*)d_in[4];
    const float* geno_b   = (const float*)d_in[5];
    const float* w1       = (const float*)d_in[6];
    const float* b1       = (const float*)d_in[7];
    const float* w2       = (const float*)d_in[8];
    const float* b2       = (const float*)d_in[9];
    float* out = (float*)d_out;

    const int smem_bytes = (2 * STAGE_FLOATS) * 4 + BM * 8;
    cudaFuncSetAttribute(ffn1_mma_kernel, cudaFuncAttributeMaxDynamicSharedMemorySize, smem_bytes);

    zero_kernel<<<64, 512>>>();
    glog_kernel<<<1, 64>>>(geno_vec, geno_w, geno_b);
    gate_kernel<<<(BB * NN + 7) / 8, 256>>>(tokens, gate_w, gate_b);
    {
        dim3 g(CC / BN, NN / BM, BB * KK);  // 4 x 16 x 64, early-exit on empty m-tiles
        ffn1_mma_kernel<<<g, 256, smem_bytes>>>(tokens, w1, b1);
    }
    centers_kernel<<<BB * KK, 512>>>(w2, b2, out, out_size);
    loss_kernel<<<1, 1>>>(out, out_size);
}